// round 3
// baseline (speedup 1.0000x reference)
#include <cuda_runtime.h>
#include <math.h>

#define BATCH 2048
#define SEQ   128
#define HID   512
#define TOUT  24
#define MROWS 16    // batch rows per CTA
#define NTHR  128
#define NPT   4     // hidden outputs per thread (128*4 = 512)

typedef unsigned long long u64;

// Transposed weight scratch (device globals: no allocation, graph-safe).
__device__ float g_eT[HID * HID];
__device__ float g_dT[HID * HID];

__device__ __forceinline__ u64 bcast2(float v) {
    u64 r;
    asm("mov.b64 %0, {%1, %1};" : "=l"(r) : "r"(__float_as_uint(v)));
    return r;
}
__device__ __forceinline__ u64 pack2(float lo, float hi) {
    u64 r;
    asm("mov.b64 %0, {%1, %2};" : "=l"(r) : "r"(__float_as_uint(lo)), "r"(__float_as_uint(hi)));
    return r;
}
__device__ __forceinline__ u64 ffma2(u64 a, u64 b, u64 c) {
    u64 d;
    asm("fma.rn.f32x2 %0, %1, %2, %3;" : "=l"(d) : "l"(a), "l"(b), "l"(c));
    return d;
}
__device__ __forceinline__ u64 fadd2(u64 a, u64 b) {
    u64 d;
    asm("add.rn.f32x2 %0, %1, %2;" : "=l"(d) : "l"(a), "l"(b));
    return d;
}
__device__ __forceinline__ void unpack2(u64 v, float& lo, float& hi) {
    unsigned a, b;
    asm("mov.b64 {%0, %1}, %2;" : "=r"(a), "=r"(b) : "l"(v));
    lo = __uint_as_float(a);
    hi = __uint_as_float(b);
}

// Transpose both 512x512 recurrent matrices: g_eT[k*512+n] = eW[n*512+k], same for dW.
// Makes mainloop weight loads fully coalesced (avoids the 32-lines-per-LDG L1tex trap).
__global__ void transpose_both(const float* __restrict__ eW, const float* __restrict__ dW) {
    __shared__ float tile[32][33];
    const float* src = blockIdx.z ? dW : eW;
    float* dst = blockIdx.z ? g_dT : g_eT;
    int k = blockIdx.x * 32 + threadIdx.x;
    int n = blockIdx.y * 32 + threadIdx.y;
    #pragma unroll
    for (int i = 0; i < 32; i += 8)
        tile[threadIdx.y + i][threadIdx.x] = src[(n + i) * HID + k];
    __syncthreads();
    int n2 = blockIdx.y * 32 + threadIdx.x;
    int k2 = blockIdx.x * 32 + threadIdx.y;
    #pragma unroll
    for (int i = 0; i < 32; i += 8)
        dst[(k2 + i) * HID + n2] = tile[threadIdx.x][threadIdx.y + i];
}

__global__ __launch_bounds__(NTHR, 1)
void rnn_kernel(const float* __restrict__ x,
                const float* __restrict__ eWih,
                const float* __restrict__ ebih, const float* __restrict__ ebhh,
                const float* __restrict__ dWih,
                const float* __restrict__ dbih, const float* __restrict__ dbhh,
                const float* __restrict__ fcW, const float* __restrict__ fcb,
                float* __restrict__ out)
{
    // h state: k-major, 16 batch rows contiguous per hidden index (64B rows, 16B aligned).
    __shared__ __align__(16) float hbuf[HID][MROWS];   // 32 KB
    __shared__ __align__(16) float xs[SEQ][MROWS];     // 8 KB (per-CTA input tile)
    __shared__ __align__(16) float dinp[MROWS];
    __shared__ float red[4][MROWS];

    const int tid = threadIdx.x;
    const int b0 = blockIdx.x * MROWS;
    const int n0 = tid * NPT;

    // h0 = 0
    for (int i = tid; i < HID * MROWS / 4; i += NTHR)
        ((float4*)hbuf)[i] = make_float4(0.f, 0.f, 0.f, 0.f);
    // xs[s][m] = x[(b0+m)*SEQ + s]  (coalesced: one row per sweep)
    for (int i = tid; i < MROWS * SEQ; i += NTHR) {
        int m = i >> 7;           // SEQ == 128
        int s = i & (SEQ - 1);
        xs[s][m] = x[(b0 + m) * SEQ + s];
    }

    // Per-thread constant weights for its 4 hidden units.
    float4 wihE = *(const float4*)(eWih + n0);
    float4 bA = *(const float4*)(ebih + n0);
    float4 bB = *(const float4*)(ebhh + n0);
    float4 biasE = make_float4(bA.x + bB.x, bA.y + bB.y, bA.z + bB.z, bA.w + bB.w);
    float4 wihD = *(const float4*)(dWih + n0);
    float4 dA = *(const float4*)(dbih + n0);
    float4 dB = *(const float4*)(dbhh + n0);
    float4 biasD = make_float4(dA.x + dB.x, dA.y + dB.y, dA.z + dB.z, dA.w + dB.w);
    const float fcb0 = fcb[0];

    __syncthreads();

    // One recurrent step: h_new = tanh(inp*wih + bias + h @ Whh^T), all in fp32x2.
    auto step = [&](const float* __restrict__ Wt, const float4 wih, const float4 bias,
                    const float* __restrict__ inp) {
        u64 acc[NPT][8];
        #pragma unroll
        for (int n = 0; n < NPT; n++)
            #pragma unroll
            for (int p = 0; p < 8; p++) acc[n][p] = 0ULL;

        const float* wp = Wt + n0;  // Wt[k*HID + n], thread owns n0..n0+3 -> coalesced float4
        float4 wc[4];
        #pragma unroll
        for (int j = 0; j < 4; j++) wc[j] = *(const float4*)(wp + j * HID);

        #pragma unroll 1
        for (int k0 = 0; k0 < HID; k0 += 4) {
            // software-pipeline next weight chunk (covers ~L2 latency with one warp/SMSP)
            const int kp = (k0 + 4) & (HID - 1);
            float4 wn[4];
            #pragma unroll
            for (int j = 0; j < 4; j++) wn[j] = *(const float4*)(wp + (kp + j) * HID);

            #pragma unroll
            for (int j = 0; j < 4; j++) {
                const u64 w0 = bcast2(wc[j].x);
                const u64 w1 = bcast2(wc[j].y);
                const u64 w2 = bcast2(wc[j].z);
                const u64 w3 = bcast2(wc[j].w);
                const ulonglong2* hp = (const ulonglong2*)&hbuf[k0 + j][0]; // warp-broadcast LDS
                #pragma unroll
                for (int q = 0; q < 4; q++) {
                    ulonglong2 hv = hp[q];
                    acc[0][2*q]   = ffma2(hv.x, w0, acc[0][2*q]);
                    acc[0][2*q+1] = ffma2(hv.y, w0, acc[0][2*q+1]);
                    acc[1][2*q]   = ffma2(hv.x, w1, acc[1][2*q]);
                    acc[1][2*q+1] = ffma2(hv.y, w1, acc[1][2*q+1]);
                    acc[2][2*q]   = ffma2(hv.x, w2, acc[2][2*q]);
                    acc[2][2*q+1] = ffma2(hv.y, w2, acc[2][2*q+1]);
                    acc[3][2*q]   = ffma2(hv.x, w3, acc[3][2*q]);
                    acc[3][2*q+1] = ffma2(hv.y, w3, acc[3][2*q+1]);
                }
            }
            #pragma unroll
            for (int j = 0; j < 4; j++) wc[j] = wn[j];
        }

        __syncthreads();  // all hbuf reads for this step complete

        const u64* xp = (const u64*)inp;
        const float wihv[4]  = {wih.x, wih.y, wih.z, wih.w};
        const float biasv[4] = {bias.x, bias.y, bias.z, bias.w};
        #pragma unroll
        for (int n = 0; n < NPT; n++) {
            const u64 wih2  = bcast2(wihv[n]);
            const u64 bias2 = bcast2(biasv[n]);
            u64* hrow = (u64*)&hbuf[n0 + n][0];
            #pragma unroll
            for (int p = 0; p < 8; p++) {
                u64 v = ffma2(xp[p], wih2, fadd2(acc[n][p], bias2));
                float lo, hi;
                unpack2(v, lo, hi);
                hrow[p] = pack2(tanhf(lo), tanhf(hi));
            }
        }
        __syncthreads();  // h_new visible
    };

    // ---- encoder: 128 steps ----
    #pragma unroll 1
    for (int t = 0; t < SEQ; t++)
        step(g_eT, wihE, biasE, &xs[t][0]);

    // ---- decoder: 24 steps with fc head + feedback ----
    if (tid < MROWS) dinp[tid] = xs[SEQ - 1][tid];
    __syncthreads();

    #pragma unroll 1
    for (int t = 0; t < TOUT; t++) {
        step(g_dT, wihD, biasD, dinp);

        // fc: out[m] = sum_k h2[k][m] * fcW[k] + fcb  (64 threads, 4 k-slices x 16 rows)
        if (tid < 64) {
            const int m = tid & (MROWS - 1);
            const int sl = tid >> 4;
            float s = 0.f;
            const float* fw = fcW + sl * 128;
            #pragma unroll 4
            for (int k = 0; k < 128; k++)
                s = fmaf(hbuf[sl * 128 + k][m], fw[k], s);
            red[sl][m] = s;
        }
        __syncthreads();
        if (tid < MROWS) {
            float o = red[0][tid] + red[1][tid] + red[2][tid] + red[3][tid] + fcb0;
            dinp[tid] = o;                       // feedback input for next step
            out[(b0 + tid) * TOUT + t] = o;
        }
        __syncthreads();
    }
}

extern "C" void kernel_launch(void* const* d_in, const int* in_sizes, int n_in,
                              void* d_out, int out_size) {
    (void)in_sizes; (void)n_in; (void)out_size;
    const float* x    = (const float*)d_in[0];
    const float* eWih = (const float*)d_in[1];
    const float* eWhh = (const float*)d_in[2];
    const float* ebih = (const float*)d_in[3];
    const float* ebhh = (const float*)d_in[4];
    const float* dWih = (const float*)d_in[5];
    const float* dWhh = (const float*)d_in[6];
    const float* dbih = (const float*)d_in[7];
    const float* dbhh = (const float*)d_in[8];
    const float* fcW  = (const float*)d_in[9];
    const float* fcb  = (const float*)d_in[10];

    dim3 tgrid(HID / 32, HID / 32, 2);
    dim3 tblk(32, 8, 1);
    transpose_both<<<tgrid, tblk>>>(eWhh, dWhh);

    rnn_kernel<<<BATCH / MROWS, NTHR>>>(x, eWih, ebih, ebhh,
                                        dWih, dbih, dbhh,
                                        fcW, fcb, (float*)d_out);
}

// round 4
// speedup vs baseline: 1.1140x; 1.1140x over previous
#include <cuda_runtime.h>
#include <math.h>

#define BATCH 2048
#define SEQ   128
#define HID   512
#define TOUT  24
#define MROWS 16    // batch rows per CTA
#define NTHR  256   // 8 warps -> 2 warps per SMSP (latency hiding)
#define NPT   2     // hidden outputs per thread (256*2 = 512)
#define KCH   8     // k-chunk width (prefetch exposure ~512 cyc >= L2 lat)

typedef unsigned long long u64;

// Transposed weight scratch (device globals: no allocation, graph-safe).
__device__ float g_eT[HID * HID];
__device__ float g_dT[HID * HID];

__device__ __forceinline__ u64 bcast2(float v) {
    u64 r;
    asm("mov.b64 %0, {%1, %1};" : "=l"(r) : "r"(__float_as_uint(v)));
    return r;
}
__device__ __forceinline__ u64 pack2(float lo, float hi) {
    u64 r;
    asm("mov.b64 %0, {%1, %2};" : "=l"(r) : "r"(__float_as_uint(lo)), "r"(__float_as_uint(hi)));
    return r;
}
__device__ __forceinline__ u64 ffma2(u64 a, u64 b, u64 c) {
    u64 d;
    asm("fma.rn.f32x2 %0, %1, %2, %3;" : "=l"(d) : "l"(a), "l"(b), "l"(c));
    return d;
}
__device__ __forceinline__ u64 fadd2(u64 a, u64 b) {
    u64 d;
    asm("add.rn.f32x2 %0, %1, %2;" : "=l"(d) : "l"(a), "l"(b));
    return d;
}
__device__ __forceinline__ void unpack2(u64 v, float& lo, float& hi) {
    unsigned a, b;
    asm("mov.b64 {%0, %1}, %2;" : "=r"(a), "=r"(b) : "l"(v));
    lo = __uint_as_float(a);
    hi = __uint_as_float(b);
}

// Transpose both 512x512 recurrent matrices: g_eT[k*512+n] = eW[n*512+k].
__global__ void transpose_both(const float* __restrict__ eW, const float* __restrict__ dW) {
    __shared__ float tile[32][33];
    const float* src = blockIdx.z ? dW : eW;
    float* dst = blockIdx.z ? g_dT : g_eT;
    int k = blockIdx.x * 32 + threadIdx.x;
    int n = blockIdx.y * 32 + threadIdx.y;
    #pragma unroll
    for (int i = 0; i < 32; i += 8)
        tile[threadIdx.y + i][threadIdx.x] = src[(n + i) * HID + k];
    __syncthreads();
    int n2 = blockIdx.y * 32 + threadIdx.x;
    int k2 = blockIdx.x * 32 + threadIdx.y;
    #pragma unroll
    for (int i = 0; i < 32; i += 8)
        dst[(k2 + i) * HID + n2] = tile[threadIdx.x][threadIdx.y + i];
}

__global__ __launch_bounds__(NTHR, 1)
void rnn_kernel(const float* __restrict__ x,
                const float* __restrict__ eWih,
                const float* __restrict__ ebih, const float* __restrict__ ebhh,
                const float* __restrict__ dWih,
                const float* __restrict__ dbih, const float* __restrict__ dbhh,
                const float* __restrict__ fcW, const float* __restrict__ fcb,
                float* __restrict__ out)
{
    // h state: k-major, 16 batch rows contiguous per hidden index.
    __shared__ __align__(16) float hbuf[HID][MROWS];   // 32 KB
    __shared__ __align__(16) float xs[SEQ][MROWS];     // 8 KB
    __shared__ __align__(16) float dinp[MROWS];
    __shared__ float red[4][MROWS];

    const int tid = threadIdx.x;
    const int b0 = blockIdx.x * MROWS;
    const int n0 = tid * NPT;

    // h0 = 0
    for (int i = tid; i < HID * MROWS / 4; i += NTHR)
        ((float4*)hbuf)[i] = make_float4(0.f, 0.f, 0.f, 0.f);
    // xs[s][m] = x[(b0+m)*SEQ + s]
    for (int i = tid; i < MROWS * SEQ; i += NTHR) {
        int m = i >> 7;           // SEQ == 128
        int s = i & (SEQ - 1);
        xs[s][m] = x[(b0 + m) * SEQ + s];
    }

    // Per-thread constants for its 2 hidden units.
    float2 wihE = *(const float2*)(eWih + n0);
    float2 eA = *(const float2*)(ebih + n0);
    float2 eB = *(const float2*)(ebhh + n0);
    float2 biasE = make_float2(eA.x + eB.x, eA.y + eB.y);
    float2 wihD = *(const float2*)(dWih + n0);
    float2 dA = *(const float2*)(dbih + n0);
    float2 dB = *(const float2*)(dbhh + n0);
    float2 biasD = make_float2(dA.x + dB.x, dA.y + dB.y);
    const float fcb0 = fcb[0];

    __syncthreads();

    // One recurrent step: h_new = tanh(inp*wih + bias + h @ Whh^T), fp32x2.
    auto step = [&](const float* __restrict__ Wt, const float2 wih, const float2 bias,
                    const float* __restrict__ inp) {
        u64 acc[NPT][8];
        #pragma unroll
        for (int n = 0; n < NPT; n++)
            #pragma unroll
            for (int p = 0; p < 8; p++) acc[n][p] = 0ULL;

        // Wt[k*HID + n0..n0+1]: coalesced float2 per k (warp covers 256B/row).
        const float2* wp = (const float2*)(Wt + n0);
        float2 wc[KCH], wn[KCH];
        #pragma unroll
        for (int j = 0; j < KCH; j++) wc[j] = wp[j * (HID / 2)];

        #pragma unroll 1
        for (int k0 = 0; k0 < HID; k0 += KCH) {
            const int kp = (k0 + KCH) & (HID - 1);   // depth-1 prefetch of next chunk
            #pragma unroll
            for (int j = 0; j < KCH; j++) wn[j] = wp[(kp + j) * (HID / 2)];

            #pragma unroll
            for (int j = 0; j < KCH; j++) {
                const u64 w0 = bcast2(wc[j].x);
                const u64 w1 = bcast2(wc[j].y);
                const ulonglong2* hp = (const ulonglong2*)&hbuf[k0 + j][0]; // broadcast LDS
                #pragma unroll
                for (int q = 0; q < 4; q++) {
                    ulonglong2 hv = hp[q];
                    acc[0][2*q]   = ffma2(hv.x, w0, acc[0][2*q]);
                    acc[0][2*q+1] = ffma2(hv.y, w0, acc[0][2*q+1]);
                    acc[1][2*q]   = ffma2(hv.x, w1, acc[1][2*q]);
                    acc[1][2*q+1] = ffma2(hv.y, w1, acc[1][2*q+1]);
                }
            }
            #pragma unroll
            for (int j = 0; j < KCH; j++) wc[j] = wn[j];
        }

        __syncthreads();  // all hbuf reads done

        const u64* xp = (const u64*)inp;
        const float wihv[2]  = {wih.x, wih.y};
        const float biasv[2] = {bias.x, bias.y};
        #pragma unroll
        for (int n = 0; n < NPT; n++) {
            const u64 wih2  = bcast2(wihv[n]);
            const u64 bias2 = bcast2(biasv[n]);
            u64* hrow = (u64*)&hbuf[n0 + n][0];
            #pragma unroll
            for (int p = 0; p < 8; p++) {
                u64 v = ffma2(xp[p], wih2, fadd2(acc[n][p], bias2));
                float lo, hi;
                unpack2(v, lo, hi);
                hrow[p] = pack2(tanhf(lo), tanhf(hi));
            }
        }
        __syncthreads();  // h_new visible
    };

    // ---- encoder: 128 steps ----
    #pragma unroll 1
    for (int t = 0; t < SEQ; t++)
        step(g_eT, wihE, biasE, &xs[t][0]);

    // ---- decoder: 24 steps with fc head + feedback ----
    if (tid < MROWS) dinp[tid] = xs[SEQ - 1][tid];
    __syncthreads();

    #pragma unroll 1
    for (int t = 0; t < TOUT; t++) {
        step(g_dT, wihD, biasD, dinp);

        // fc: out[m] = sum_k h2[k][m] * fcW[k] + fcb
        if (tid < 64) {
            const int m = tid & (MROWS - 1);
            const int sl = tid >> 4;
            float s = 0.f;
            const float* fw = fcW + sl * 128;
            #pragma unroll 4
            for (int k = 0; k < 128; k++)
                s = fmaf(hbuf[sl * 128 + k][m], fw[k], s);
            red[sl][m] = s;
        }
        __syncthreads();
        if (tid < MROWS) {
            float o = red[0][tid] + red[1][tid] + red[2][tid] + red[3][tid] + fcb0;
            dinp[tid] = o;
            out[(b0 + tid) * TOUT + t] = o;
        }
        __syncthreads();
    }
}

extern "C" void kernel_launch(void* const* d_in, const int* in_sizes, int n_in,
                              void* d_out, int out_size) {
    (void)in_sizes; (void)n_in; (void)out_size;
    const float* x    = (const float*)d_in[0];
    const float* eWih = (const float*)d_in[1];
    const float* eWhh = (const float*)d_in[2];
    const float* ebih = (const float*)d_in[3];
    const float* ebhh = (const float*)d_in[4];
    const float* dWih = (const float*)d_in[5];
    const float* dWhh = (const float*)d_in[6];
    const float* dbih = (const float*)d_in[7];
    const float* dbhh = (const float*)d_in[8];
    const float* fcW  = (const float*)d_in[9];
    const float* fcb  = (const float*)d_in[10];

    dim3 tgrid(HID / 32, HID / 32, 2);
    dim3 tblk(32, 8, 1);
    transpose_both<<<tgrid, tblk>>>(eWhh, dWhh);

    rnn_kernel<<<BATCH / MROWS, NTHR>>>(x, eWih, ebih, ebhh,
                                        dWih, dbih, dbhh,
                                        fcW, fcb, (float*)d_out);
}